// round 7
// baseline (speedup 1.0000x reference)
#include <cuda_runtime.h>

#define B_      256
#define T_      24
#define D_      2
#define N_      512
#define H_      128
#define G_      384            // 3*H
#define COLS    64             // columns per CTA
#define THREADS 256
#define CTAS    (B_ * N_ / COLS)   // 2048

typedef unsigned long long ull;

__device__ __forceinline__ ull pack2(float x, float y) {
    ull r; asm("mov.b64 %0, {%1, %2};" : "=l"(r) : "f"(x), "f"(y)); return r;
}
__device__ __forceinline__ float2 unpk(ull a) {
    float2 f; asm("mov.b64 {%0, %1}, %2;" : "=f"(f.x), "=f"(f.y) : "l"(a)); return f;
}
__device__ __forceinline__ void fma2(ull &d, ull a, ull b) {
    asm("fma.rn.f32x2 %0, %1, %2, %0;" : "+l"(d) : "l"(a), "l"(b));
}
__device__ __forceinline__ float sigm(float v) {
    return __fdividef(1.0f, 1.0f + __expf(-v));
}
__device__ __forceinline__ float tanh_(float v) {
    return fmaf(2.0f, sigm(2.0f * v), -1.0f);
}

// Accumulate one 64-row k-tile: aG[h'] += W[k, gate*128 + hb + h'] * h[k]
// Wt: smem [64][384] row-major; hs: smem rows [64][COLS] (this k-tile's slice)
__device__ __forceinline__ void accum_tile(const float* __restrict__ Wt,
                                           const float* __restrict__ hs,
                                           int c, int hb,
                                           ull* aR, ull* aZ, ull* aN)
{
    #pragma unroll 2
    for (int kk = 0; kk < 64; ++kk) {
        float hk = hs[kk * COLS + c];
        ull h2 = pack2(hk, hk);
        const ulonglong2* wr = reinterpret_cast<const ulonglong2*>(Wt + kk * G_ + hb);
        const ulonglong2* wz = reinterpret_cast<const ulonglong2*>(Wt + kk * G_ + H_ + hb);
        const ulonglong2* wn = reinterpret_cast<const ulonglong2*>(Wt + kk * G_ + 2 * H_ + hb);
        #pragma unroll
        for (int j = 0; j < 8; ++j) {
            ulonglong2 w = wr[j];
            fma2(aR[2 * j], w.x, h2); fma2(aR[2 * j + 1], w.y, h2);
        }
        #pragma unroll
        for (int j = 0; j < 8; ++j) {
            ulonglong2 w = wz[j];
            fma2(aZ[2 * j], w.x, h2); fma2(aZ[2 * j + 1], w.y, h2);
        }
        #pragma unroll
        for (int j = 0; j < 8; ++j) {
            ulonglong2 w = wn[j];
            fma2(aN[2 * j], w.x, h2); fma2(aN[2 * j + 1], w.y, h2);
        }
    }
}

__global__ void __launch_bounds__(THREADS, 1)
gru_stack_kernel(const float* __restrict__ x,
                 const float* __restrict__ Wx0, const float* __restrict__ Wh0,
                 const float* __restrict__ bx0, const float* __restrict__ bh0,
                 const float* __restrict__ Wx1, const float* __restrict__ Wh1,
                 const float* __restrict__ bx1, const float* __restrict__ bh1,
                 float* __restrict__ out)
{
    extern __shared__ float sm[];
    float* Wt   = sm;                        // 64*384 floats (96 KB)
    float* h0s  = Wt + 64 * G_;              // [128][COLS]
    float* h1s  = h0s + H_ * COLS;           // [128][COLS]
    float* wx0s = h1s + H_ * COLS;           // [2][384]
    float* bx0s = wx0s + D_ * G_;
    float* bh0s = bx0s + G_;
    float* bx1s = bh0s + G_;
    float* bh1s = bx1s + G_;

    const int tid = threadIdx.x;
    const int c   = tid & (COLS - 1);        // column within CTA
    const int hb  = (tid >> 6) * 32;         // h-rows [hb, hb+32)

    const int col0 = blockIdx.x * COLS;
    const int bb = col0 / N_;                // CTA lies within one batch index
    const int nn = (col0 % N_) + c;

    // stage small constants + zero state
    for (int i = tid; i < D_ * G_; i += THREADS) wx0s[i] = Wx0[i];
    for (int i = tid; i < G_; i += THREADS) {
        bx0s[i] = bx0[i]; bh0s[i] = bh0[i]; bx1s[i] = bx1[i]; bh1s[i] = bh1[i];
    }
    for (int i = tid; i < H_ * COLS; i += THREADS) { h0s[i] = 0.0f; h1s[i] = 0.0f; }

    ull aR[16], aZ[16], aN[16], aN2[16];

    for (int t = 0; t < T_; ++t) {
        // ================= layer 0: gh0 = Wh0^T h0 =================
        #pragma unroll
        for (int i = 0; i < 16; ++i) { aR[i] = 0ull; aZ[i] = 0ull; aN[i] = 0ull; }
        #pragma unroll 1
        for (int kt = 0; kt < 2; ++kt) {
            __syncthreads();
            {
                const float4* src = reinterpret_cast<const float4*>(Wh0 + kt * 64 * G_);
                float4* dst = reinterpret_cast<float4*>(Wt);
                #pragma unroll 1
                for (int i = tid; i < 64 * G_ / 4; i += THREADS) dst[i] = src[i];
            }
            __syncthreads();
            accum_tile(Wt, h0s + kt * 64 * COLS, c, hb, aR, aZ, aN);
        }
        __syncthreads();   // all accum reads of h0s complete before epilogue writes

        // ---- epilogue layer 0: gates + state update, h0new -> h0s ----
        {
            const float x0 = __ldg(&x[((bb * T_ + t) * D_ + 0) * N_ + nn]);
            const float x1 = __ldg(&x[((bb * T_ + t) * D_ + 1) * N_ + nn]);
            #pragma unroll
            for (int i = 0; i < 16; ++i) {
                float2 gr = unpk(aR[i]), gz = unpk(aZ[i]), gn = unpk(aN[i]);
                float grv[2] = {gr.x, gr.y};
                float gzv[2] = {gz.x, gz.y};
                float gnv[2] = {gn.x, gn.y};
                #pragma unroll
                for (int e = 0; e < 2; ++e) {
                    int h = hb + 2 * i + e;
                    float ir = fmaf(x1, wx0s[G_ + h],          fmaf(x0, wx0s[h],          bx0s[h]));
                    float iz = fmaf(x1, wx0s[G_ + H_ + h],     fmaf(x0, wx0s[H_ + h],     bx0s[H_ + h]));
                    float in_= fmaf(x1, wx0s[G_ + 2*H_ + h],   fmaf(x0, wx0s[2*H_ + h],   bx0s[2*H_ + h]));
                    float r = sigm(ir + grv[e] + bh0s[h]);
                    float z = sigm(iz + gzv[e] + bh0s[H_ + h]);
                    float n = tanh_(fmaf(r, gnv[e] + bh0s[2*H_ + h], in_));
                    float hold = h0s[h * COLS + c];
                    h0s[h * COLS + c] = fmaf(z, hold - n, n);   // (1-z)*n + z*h
                }
            }
        }

        // ================= layer 1: gi1 = Wx1^T h0new =================
        #pragma unroll
        for (int i = 0; i < 16; ++i) { aR[i] = 0ull; aZ[i] = 0ull; aN[i] = 0ull; }
        #pragma unroll 1
        for (int kt = 0; kt < 2; ++kt) {
            __syncthreads();   // also orders h0s epilogue writes before reads below
            {
                const float4* src = reinterpret_cast<const float4*>(Wx1 + kt * 64 * G_);
                float4* dst = reinterpret_cast<float4*>(Wt);
                #pragma unroll 1
                for (int i = tid; i < 64 * G_ / 4; i += THREADS) dst[i] = src[i];
            }
            __syncthreads();
            accum_tile(Wt, h0s + kt * 64 * COLS, c, hb, aR, aZ, aN);
        }
        // ================= layer 1: gh1 = Wh1^T h1 (r,z fused into aR,aZ) ==
        #pragma unroll
        for (int i = 0; i < 16; ++i) aN2[i] = 0ull;
        #pragma unroll 1
        for (int kt = 0; kt < 2; ++kt) {
            __syncthreads();
            {
                const float4* src = reinterpret_cast<const float4*>(Wh1 + kt * 64 * G_);
                float4* dst = reinterpret_cast<float4*>(Wt);
                #pragma unroll 1
                for (int i = tid; i < 64 * G_ / 4; i += THREADS) dst[i] = src[i];
            }
            __syncthreads();
            accum_tile(Wt, h1s + kt * 64 * COLS, c, hb, aR, aZ, aN2);
        }
        __syncthreads();   // all accum reads of h1s complete before epilogue writes

        // ---- epilogue layer 1 ----
        #pragma unroll
        for (int i = 0; i < 16; ++i) {
            float2 gr = unpk(aR[i]), gz = unpk(aZ[i]), gn = unpk(aN[i]), gn2 = unpk(aN2[i]);
            float grv[2]  = {gr.x,  gr.y};
            float gzv[2]  = {gz.x,  gz.y};
            float gnv[2]  = {gn.x,  gn.y};
            float gn2v[2] = {gn2.x, gn2.y};
            #pragma unroll
            for (int e = 0; e < 2; ++e) {
                int h = hb + 2 * i + e;
                float r = sigm(grv[e] + bx1s[h] + bh1s[h]);
                float z = sigm(gzv[e] + bx1s[H_ + h] + bh1s[H_ + h]);
                float n = tanh_(fmaf(r, gn2v[e] + bh1s[2*H_ + h], gnv[e] + bx1s[2*H_ + h]));
                float hold = h1s[h * COLS + c];
                h1s[h * COLS + c] = fmaf(z, hold - n, n);
            }
        }
    }

    __syncthreads();
    // output [2, B, H, N]: out[0]=h0 final, out[1]=h1 final
    const long ob = (long)bb * H_ * N_ + (col0 % N_);
    for (int i = tid; i < H_ * COLS; i += THREADS) {
        int h = i / COLS, cc = i - (i / COLS) * COLS;
        out[ob + (long)h * N_ + cc] = h0s[i];
        out[(long)B_ * H_ * N_ + ob + (long)h * N_ + cc] = h1s[i];
    }
}

extern "C" void kernel_launch(void* const* d_in, const int* in_sizes, int n_in,
                              void* d_out, int out_size)
{
    (void)in_sizes; (void)n_in; (void)out_size;
    const float* x   = (const float*)d_in[0];
    const float* Wx0 = (const float*)d_in[1];
    const float* Wh0 = (const float*)d_in[2];
    const float* bx0 = (const float*)d_in[3];
    const float* bh0 = (const float*)d_in[4];
    const float* Wx1 = (const float*)d_in[5];
    const float* Wh1 = (const float*)d_in[6];
    const float* bx1 = (const float*)d_in[7];
    const float* bh1 = (const float*)d_in[8];
    float* out = (float*)d_out;

    const int smem_bytes = (64 * G_ + 2 * H_ * COLS + D_ * G_ + 4 * G_) * 4;  // 173056
    cudaFuncSetAttribute(gru_stack_kernel,
                         cudaFuncAttributeMaxDynamicSharedMemorySize, smem_bytes);
    gru_stack_kernel<<<CTAS, THREADS, smem_bytes>>>(
        x, Wx0, Wh0, bx0, bh0, Wx1, Wh1, bx1, bh1, out);
}

// round 11
// speedup vs baseline: 1.8659x; 1.8659x over previous
#include <cuda_runtime.h>
#include <cstdint>

#define B_      256
#define T_      24
#define D_      2
#define N_      512
#define H_      128
#define G_      384                 // 3*H
#define COLS    64                  // columns per CTA
#define THREADS 256
#define CTAS    (B_ * N_ / COLS)    // 2048
#define TROWS   32                  // k-rows per staged weight tile
#define TILE_FLOATS (TROWS * G_)    // 12288
#define TILE_BYTES  (TILE_FLOATS * 4) // 49152

typedef unsigned long long ull;

__device__ __forceinline__ ull pack2(float x, float y) {
    ull r; asm("mov.b64 %0, {%1, %2};" : "=l"(r) : "f"(x), "f"(y)); return r;
}
__device__ __forceinline__ float2 unpk(ull a) {
    float2 f; asm("mov.b64 {%0, %1}, %2;" : "=f"(f.x), "=f"(f.y) : "l"(a)); return f;
}
__device__ __forceinline__ void fma2(ull &d, ull a, ull b) {
    asm("fma.rn.f32x2 %0, %1, %2, %0;" : "+l"(d) : "l"(a), "l"(b));
}
__device__ __forceinline__ float sigm(float v) {
    return __fdividef(1.0f, 1.0f + __expf(-v));
}
__device__ __forceinline__ float tanh_(float v) {
    return fmaf(2.0f, sigm(2.0f * v), -1.0f);
}

// One 32-row k-tile. Thread owns 2 adjacent columns (2*c2, 2*c2+1) and 16
// h-rows [hb, hb+16). Weights loaded once, reused for both columns.
// Accum layout: aG[col*8 + pair], pair p covers h rows {hb+2p, hb+2p+1}.
__device__ __forceinline__ void accum_tile(const float* __restrict__ Wt,
                                           const float* __restrict__ hs,
                                           int c2, int hb,
                                           ull* aR, ull* aZ, ull* aN)
{
    #pragma unroll 2
    for (int kk = 0; kk < TROWS; ++kk) {
        float2 hv = *reinterpret_cast<const float2*>(hs + kk * COLS + 2 * c2);
        ull h0 = pack2(hv.x, hv.x);
        ull h1 = pack2(hv.y, hv.y);
        const ulonglong2* wr = reinterpret_cast<const ulonglong2*>(Wt + kk * G_ + hb);
        const ulonglong2* wz = reinterpret_cast<const ulonglong2*>(Wt + kk * G_ + H_ + hb);
        const ulonglong2* wn = reinterpret_cast<const ulonglong2*>(Wt + kk * G_ + 2 * H_ + hb);
        #pragma unroll
        for (int j = 0; j < 4; ++j) {
            ulonglong2 w = wr[j];
            fma2(aR[2*j],     w.x, h0); fma2(aR[2*j + 1],     w.y, h0);
            fma2(aR[8 + 2*j], w.x, h1); fma2(aR[8 + 2*j + 1], w.y, h1);
        }
        #pragma unroll
        for (int j = 0; j < 4; ++j) {
            ulonglong2 w = wz[j];
            fma2(aZ[2*j],     w.x, h0); fma2(aZ[2*j + 1],     w.y, h0);
            fma2(aZ[8 + 2*j], w.x, h1); fma2(aZ[8 + 2*j + 1], w.y, h1);
        }
        #pragma unroll
        for (int j = 0; j < 4; ++j) {
            ulonglong2 w = wn[j];
            fma2(aN[2*j],     w.x, h0); fma2(aN[2*j + 1],     w.y, h0);
            fma2(aN[8 + 2*j], w.x, h1); fma2(aN[8 + 2*j + 1], w.y, h1);
        }
    }
}

__device__ __forceinline__ void prefetch_tile(uint32_t sdst, const float* gsrc, int tid) {
    const char* g = reinterpret_cast<const char*>(gsrc) + tid * 16;
    uint32_t s = sdst + tid * 16;
    #pragma unroll
    for (int i = 0; i < 12; ++i) {   // 256 thr * 16B * 12 = 49152 B
        asm volatile("cp.async.cg.shared.global [%0], [%1], 16;"
                     :: "r"(s + i * 4096), "l"(g + i * 4096));
    }
    asm volatile("cp.async.commit_group;" ::: "memory");
}

__device__ __forceinline__ const float* tile_src(const float* Wh0, const float* Wx1,
                                                 const float* Wh1, int idx) {
    const float* b = (idx < 8) ? ((idx < 4) ? Wh0 : Wx1) : Wh1;
    return b + (idx & 3) * TILE_FLOATS;
}

__global__ void __launch_bounds__(THREADS, 1)
gru_stack_kernel(const float* __restrict__ x,
                 const float* __restrict__ Wx0, const float* __restrict__ Wh0,
                 const float* __restrict__ bx0, const float* __restrict__ bh0,
                 const float* __restrict__ Wx1, const float* __restrict__ Wh1,
                 const float* __restrict__ bx1, const float* __restrict__ bh1,
                 float* __restrict__ out)
{
    extern __shared__ float sm[];
    float* h0s  = sm + 2 * TILE_FLOATS;      // [128][64]
    float* h1s  = h0s + H_ * COLS;           // [128][64]
    float* wx0s = h1s + H_ * COLS;           // [2][384]
    float* bx0s = wx0s + D_ * G_;
    float* bh0s = bx0s + G_;
    float* bx1s = bh0s + G_;
    float* bh1s = bx1s + G_;
    const uint32_t smem_u32 = (uint32_t)__cvta_generic_to_shared(sm);

    const int tid = threadIdx.x;
    const int c2  = tid & 31;                // column-pair index: cols {2c2, 2c2+1}
    const int hb  = (tid >> 5) * 16;         // h-rows [hb, hb+16)
    const int cc  = 2 * c2;

    const int col0 = blockIdx.x * COLS;
    const int bb   = col0 / N_;
    const int nn0  = (col0 % N_) + cc;

    // kick off tile 0 (Wh0 rows 0..31) before anything else
    prefetch_tile(smem_u32, Wh0, tid);

    // stage constants + zero state
    for (int i = tid; i < D_ * G_; i += THREADS) wx0s[i] = Wx0[i];
    for (int i = tid; i < G_; i += THREADS) {
        bx0s[i] = bx0[i]; bh0s[i] = bh0[i]; bx1s[i] = bx1[i]; bh1s[i] = bh1[i];
    }
    for (int i = tid; i < H_ * COLS; i += THREADS) { h0s[i] = 0.0f; h1s[i] = 0.0f; }
    __syncthreads();

    ull aR[16], aZ[16], aN[16], aN2[16];
    int parity = 0;
    int nidx = 1;   // next tile index in the 12-tile cycle {Wh0 x4, Wx1 x4, Wh1 x4}

    auto tile_iter = [&](const float* hs, ull* aRp, ull* aZp, ull* aNp) {
        prefetch_tile(smem_u32 + (uint32_t)(parity ^ 1) * TILE_BYTES,
                      tile_src(Wh0, Wx1, Wh1, nidx), tid);
        nidx = (nidx == 11) ? 0 : nidx + 1;
        asm volatile("cp.async.wait_group 1;" ::: "memory");
        __syncthreads();                       // staged tile visible to all
        accum_tile(sm + parity * TILE_FLOATS, hs, c2, hb, aRp, aZp, aNp);
        __syncthreads();                       // all reads done before buffer reuse
        parity ^= 1;
    };

    for (int t = 0; t < T_; ++t) {
        // ===== layer 0: gh0 = Wh0^T h0 =====
        #pragma unroll
        for (int i = 0; i < 16; ++i) { aR[i] = 0ull; aZ[i] = 0ull; aN[i] = 0ull; }
        #pragma unroll 1
        for (int kt = 0; kt < 4; ++kt)
            tile_iter(h0s + kt * TROWS * COLS, aR, aZ, aN);

        // ---- epilogue layer 0 ----
        {
            const float2 xa = *reinterpret_cast<const float2*>(
                &x[((bb * T_ + t) * D_ + 0) * N_ + nn0]);
            const float2 xb = *reinterpret_cast<const float2*>(
                &x[((bb * T_ + t) * D_ + 1) * N_ + nn0]);
            #pragma unroll
            for (int p = 0; p < 8; ++p) {
                float2 r0 = unpk(aR[p]), r1 = unpk(aR[8 + p]);
                float2 z0 = unpk(aZ[p]), z1 = unpk(aZ[8 + p]);
                float2 n0 = unpk(aN[p]), n1 = unpk(aN[8 + p]);
                float rv0[2] = {r0.x, r0.y}, rv1[2] = {r1.x, r1.y};
                float zv0[2] = {z0.x, z0.y}, zv1[2] = {z1.x, z1.y};
                float nv0[2] = {n0.x, n0.y}, nv1[2] = {n1.x, n1.y};
                #pragma unroll
                for (int e = 0; e < 2; ++e) {
                    int h = hb + 2 * p + e;
                    float w0r = wx0s[h],          w1r = wx0s[G_ + h];
                    float w0z = wx0s[H_ + h],     w1z = wx0s[G_ + H_ + h];
                    float w0n = wx0s[2*H_ + h],   w1n = wx0s[G_ + 2*H_ + h];
                    float bxr = bx0s[h], bxz = bx0s[H_ + h], bxn = bx0s[2*H_ + h];
                    float bhr = bh0s[h], bhz = bh0s[H_ + h], bhn = bh0s[2*H_ + h];
                    float* hp = &h0s[h * COLS + cc];
                    float2 hold = *reinterpret_cast<float2*>(hp);
                    // col 0
                    float ir = fmaf(xb.x, w1r, fmaf(xa.x, w0r, bxr));
                    float iz = fmaf(xb.x, w1z, fmaf(xa.x, w0z, bxz));
                    float in = fmaf(xb.x, w1n, fmaf(xa.x, w0n, bxn));
                    float rr = sigm(ir + rv0[e] + bhr);
                    float zz = sigm(iz + zv0[e] + bhz);
                    float nv = tanh_(fmaf(rr, nv0[e] + bhn, in));
                    float h_new0 = fmaf(zz, hold.x - nv, nv);
                    // col 1
                    ir = fmaf(xb.y, w1r, fmaf(xa.y, w0r, bxr));
                    iz = fmaf(xb.y, w1z, fmaf(xa.y, w0z, bxz));
                    in = fmaf(xb.y, w1n, fmaf(xa.y, w0n, bxn));
                    rr = sigm(ir + rv1[e] + bhr);
                    zz = sigm(iz + zv1[e] + bhz);
                    nv = tanh_(fmaf(rr, nv1[e] + bhn, in));
                    float h_new1 = fmaf(zz, hold.y - nv, nv);
                    *reinterpret_cast<float2*>(hp) = make_float2(h_new0, h_new1);
                }
            }
        }
        // h0s writes ordered before next accum by tile_iter's pre-accum sync.

        // ===== layer 1: gi1 = Wx1^T h0new (r,z,n) =====
        #pragma unroll
        for (int i = 0; i < 16; ++i) { aR[i] = 0ull; aZ[i] = 0ull; aN[i] = 0ull; }
        #pragma unroll 1
        for (int kt = 0; kt < 4; ++kt)
            tile_iter(h0s + kt * TROWS * COLS, aR, aZ, aN);

        // ===== layer 1: gh1 = Wh1^T h1 (r,z fused into aR/aZ; n into aN2) =====
        #pragma unroll
        for (int i = 0; i < 16; ++i) aN2[i] = 0ull;
        #pragma unroll 1
        for (int kt = 0; kt < 4; ++kt)
            tile_iter(h1s + kt * TROWS * COLS, aR, aZ, aN2);

        // ---- epilogue layer 1 ----
        #pragma unroll
        for (int p = 0; p < 8; ++p) {
            float2 r0 = unpk(aR[p]), r1 = unpk(aR[8 + p]);
            float2 z0 = unpk(aZ[p]), z1 = unpk(aZ[8 + p]);
            float2 n0 = unpk(aN[p]), n1 = unpk(aN[8 + p]);
            float2 m0 = unpk(aN2[p]), m1 = unpk(aN2[8 + p]);
            float rv0[2] = {r0.x, r0.y}, rv1[2] = {r1.x, r1.y};
            float zv0[2] = {z0.x, z0.y}, zv1[2] = {z1.x, z1.y};
            float nv0[2] = {n0.x, n0.y}, nv1[2] = {n1.x, n1.y};
            float mv0[2] = {m0.x, m0.y}, mv1[2] = {m1.x, m1.y};
            #pragma unroll
            for (int e = 0; e < 2; ++e) {
                int h = hb + 2 * p + e;
                float br = bx1s[h] + bh1s[h];
                float bz = bx1s[H_ + h] + bh1s[H_ + h];
                float bxn = bx1s[2*H_ + h], bhn = bh1s[2*H_ + h];
                float* hp = &h1s[h * COLS + cc];
                float2 hold = *reinterpret_cast<float2*>(hp);
                // col 0
                float rr = sigm(rv0[e] + br);
                float zz = sigm(zv0[e] + bz);
                float nv = tanh_(fmaf(rr, mv0[e] + bhn, nv0[e] + bxn));
                float h_new0 = fmaf(zz, hold.x - nv, nv);
                // col 1
                rr = sigm(rv1[e] + br);
                zz = sigm(zv1[e] + bz);
                nv = tanh_(fmaf(rr, mv1[e] + bhn, nv1[e] + bxn));
                float h_new1 = fmaf(zz, hold.y - nv, nv);
                *reinterpret_cast<float2*>(hp) = make_float2(h_new0, h_new1);
            }
        }
    }

    asm volatile("cp.async.wait_group 0;" ::: "memory");
    __syncthreads();
    // output [2, B, H, N]
    const long ob = (long)bb * H_ * N_ + (col0 % N_);
    for (int i = tid; i < H_ * COLS; i += THREADS) {
        int h = i / COLS, c = i - (i / COLS) * COLS;
        out[ob + (long)h * N_ + c] = h0s[i];
        out[(long)B_ * H_ * N_ + ob + (long)h * N_ + c] = h1s[i];
    }
}

extern "C" void kernel_launch(void* const* d_in, const int* in_sizes, int n_in,
                              void* d_out, int out_size)
{
    (void)in_sizes; (void)n_in; (void)out_size;
    const float* x   = (const float*)d_in[0];
    const float* Wx0 = (const float*)d_in[1];
    const float* Wh0 = (const float*)d_in[2];
    const float* bx0 = (const float*)d_in[3];
    const float* bh0 = (const float*)d_in[4];
    const float* Wx1 = (const float*)d_in[5];
    const float* Wh1 = (const float*)d_in[6];
    const float* bx1 = (const float*)d_in[7];
    const float* bh1 = (const float*)d_in[8];
    float* out = (float*)d_out;

    const int smem_bytes = (2 * TILE_FLOATS + 2 * H_ * COLS + D_ * G_ + 4 * G_) * 4; // 173056
    cudaFuncSetAttribute(gru_stack_kernel,
                         cudaFuncAttributeMaxDynamicSharedMemorySize, smem_bytes);
    gru_stack_kernel<<<CTAS, THREADS, smem_bytes>>>(
        x, Wx0, Wh0, bx0, bh0, Wx1, Wh1, bx1, bh1, out);
}

// round 13
// speedup vs baseline: 2.1228x; 1.1377x over previous
#include <cuda_runtime.h>
#include <cstdint>

#define B_      256
#define T_      24
#define D_      2
#define N_      512
#define H_      128
#define G_      384                 // 3*H
#define COLS    64                  // columns per CTA
#define THREADS 256
#define CTAS    (B_ * N_ / COLS)    // 2048
#define TROWS   32                  // k-rows per staged weight tile
#define TILE_FLOATS (TROWS * G_)    // 12288
#define TILE_BYTES  (TILE_FLOATS * 4) // 49152

typedef unsigned long long ull;

__device__ __forceinline__ ull pack2(float x, float y) {
    ull r; asm("mov.b64 %0, {%1, %2};" : "=l"(r) : "f"(x), "f"(y)); return r;
}
__device__ __forceinline__ float2 unpk(ull a) {
    float2 f; asm("mov.b64 {%0, %1}, %2;" : "=f"(f.x), "=f"(f.y) : "l"(a)); return f;
}
__device__ __forceinline__ void fma2(ull &d, ull a, ull b) {
    asm("fma.rn.f32x2 %0, %1, %2, %0;" : "+l"(d) : "l"(a), "l"(b));
}
__device__ __forceinline__ float sigm(float v) {
    return __fdividef(1.0f, 1.0f + __expf(-v));
}
__device__ __forceinline__ float tanh_(float v) {
    return fmaf(2.0f, sigm(2.0f * v), -1.0f);
}

// One 32-row k-tile. Thread owns 4 adjacent columns (cc..cc+3) and 8 h-rows
// [hb, hb+8). Weights loaded once per k-row, reused across all 4 columns.
// Accum layout: aG[col*4 + q], q covers h-row pair {hb+2q, hb+2q+1}.
__device__ __forceinline__ void accum_tile(const float* __restrict__ Wt,
                                           const float* __restrict__ hs,
                                           int cc, int hb,
                                           ull* aR, ull* aZ, ull* aN)
{
    #pragma unroll 2
    for (int kk = 0; kk < TROWS; ++kk) {
        float4 hv = *reinterpret_cast<const float4*>(hs + kk * COLS + cc);
        ull h2[4];
        h2[0] = pack2(hv.x, hv.x); h2[1] = pack2(hv.y, hv.y);
        h2[2] = pack2(hv.z, hv.z); h2[3] = pack2(hv.w, hv.w);
        const ulonglong2* wr = reinterpret_cast<const ulonglong2*>(Wt + kk * G_ + hb);
        const ulonglong2* wz = reinterpret_cast<const ulonglong2*>(Wt + kk * G_ + H_ + hb);
        const ulonglong2* wn = reinterpret_cast<const ulonglong2*>(Wt + kk * G_ + 2 * H_ + hb);
        {
            ulonglong2 wa = wr[0], wb = wr[1];
            #pragma unroll
            for (int col = 0; col < 4; ++col) {
                fma2(aR[col*4+0], wa.x, h2[col]); fma2(aR[col*4+1], wa.y, h2[col]);
                fma2(aR[col*4+2], wb.x, h2[col]); fma2(aR[col*4+3], wb.y, h2[col]);
            }
        }
        {
            ulonglong2 wa = wz[0], wb = wz[1];
            #pragma unroll
            for (int col = 0; col < 4; ++col) {
                fma2(aZ[col*4+0], wa.x, h2[col]); fma2(aZ[col*4+1], wa.y, h2[col]);
                fma2(aZ[col*4+2], wb.x, h2[col]); fma2(aZ[col*4+3], wb.y, h2[col]);
            }
        }
        {
            ulonglong2 wa = wn[0], wb = wn[1];
            #pragma unroll
            for (int col = 0; col < 4; ++col) {
                fma2(aN[col*4+0], wa.x, h2[col]); fma2(aN[col*4+1], wa.y, h2[col]);
                fma2(aN[col*4+2], wb.x, h2[col]); fma2(aN[col*4+3], wb.y, h2[col]);
            }
        }
    }
}

__device__ __forceinline__ void prefetch_tile(uint32_t sdst, const float* gsrc, int tid) {
    const char* g = reinterpret_cast<const char*>(gsrc) + tid * 16;
    uint32_t s = sdst + tid * 16;
    #pragma unroll
    for (int i = 0; i < 12; ++i) {   // 256 thr * 16B * 12 = 49152 B
        asm volatile("cp.async.cg.shared.global [%0], [%1], 16;"
                     :: "r"(s + i * 4096), "l"(g + i * 4096));
    }
    asm volatile("cp.async.commit_group;" ::: "memory");
}

__device__ __forceinline__ const float* tile_src(const float* Wh0, const float* Wx1,
                                                 const float* Wh1, int idx) {
    const float* b = (idx < 8) ? ((idx < 4) ? Wh0 : Wx1) : Wh1;
    return b + (idx & 3) * TILE_FLOATS;
}

__global__ void __launch_bounds__(THREADS, 1)
gru_stack_kernel(const float* __restrict__ x,
                 const float* __restrict__ Wx0, const float* __restrict__ Wh0,
                 const float* __restrict__ bx0, const float* __restrict__ bh0,
                 const float* __restrict__ Wx1, const float* __restrict__ Wh1,
                 const float* __restrict__ bx1, const float* __restrict__ bh1,
                 float* __restrict__ out)
{
    extern __shared__ float sm[];
    float* h0s  = sm + 2 * TILE_FLOATS;      // [128][64]
    float* h1s  = h0s + H_ * COLS;           // [128][64]
    float* wx0s = h1s + H_ * COLS;           // [2][384]
    float* bx0s = wx0s + D_ * G_;
    float* bh0s = bx0s + G_;
    float* bx1s = bh0s + G_;
    float* bh1s = bx1s + G_;
    const uint32_t smem_u32 = (uint32_t)__cvta_generic_to_shared(sm);

    const int tid = threadIdx.x;
    const int cc  = (tid & 15) * 4;          // columns [cc, cc+4)
    const int hb  = (tid >> 4) * 8;          // h-rows [hb, hb+8)

    const int col0 = blockIdx.x * COLS;
    const int bb   = col0 / N_;
    const int nn0  = (col0 % N_) + cc;

    // kick off tile 0 (Wh0 rows 0..31) before anything else
    prefetch_tile(smem_u32, Wh0, tid);

    // stage constants + zero state
    for (int i = tid; i < D_ * G_; i += THREADS) wx0s[i] = Wx0[i];
    for (int i = tid; i < G_; i += THREADS) {
        bx0s[i] = bx0[i]; bh0s[i] = bh0[i]; bx1s[i] = bx1[i]; bh1s[i] = bh1[i];
    }
    for (int i = tid; i < H_ * COLS; i += THREADS) { h0s[i] = 0.0f; h1s[i] = 0.0f; }
    __syncthreads();

    ull aR[16], aZ[16], aN[16], aN2[16];
    int parity = 0;
    int nidx = 1;   // next tile index in the 12-tile cycle {Wh0 x4, Wx1 x4, Wh1 x4}

    auto tile_iter = [&](const float* hs, ull* aRp, ull* aZp, ull* aNp) {
        prefetch_tile(smem_u32 + (uint32_t)(parity ^ 1) * TILE_BYTES,
                      tile_src(Wh0, Wx1, Wh1, nidx), tid);
        nidx = (nidx == 11) ? 0 : nidx + 1;
        asm volatile("cp.async.wait_group 1;" ::: "memory");
        __syncthreads();                       // staged tile visible to all
        accum_tile(sm + parity * TILE_FLOATS, hs, cc, hb, aRp, aZp, aNp);
        __syncthreads();                       // all reads done before buffer reuse
        parity ^= 1;
    };

    for (int t = 0; t < T_; ++t) {
        // ===== layer 0: gh0 = Wh0^T h0 =====
        #pragma unroll
        for (int i = 0; i < 16; ++i) { aR[i] = 0ull; aZ[i] = 0ull; aN[i] = 0ull; }
        #pragma unroll 1
        for (int kt = 0; kt < 4; ++kt)
            tile_iter(h0s + kt * TROWS * COLS, aR, aZ, aN);

        // ---- epilogue layer 0 ----
        {
            const float4 xa = *reinterpret_cast<const float4*>(
                &x[((bb * T_ + t) * D_ + 0) * N_ + nn0]);
            const float4 xb = *reinterpret_cast<const float4*>(
                &x[((bb * T_ + t) * D_ + 1) * N_ + nn0]);
            const float xav[4] = {xa.x, xa.y, xa.z, xa.w};
            const float xbv[4] = {xb.x, xb.y, xb.z, xb.w};
            #pragma unroll
            for (int q = 0; q < 4; ++q) {
                float2 gr[4], gz[4], gn[4];
                #pragma unroll
                for (int col = 0; col < 4; ++col) {
                    gr[col] = unpk(aR[col*4+q]);
                    gz[col] = unpk(aZ[col*4+q]);
                    gn[col] = unpk(aN[col*4+q]);
                }
                #pragma unroll
                for (int e = 0; e < 2; ++e) {
                    const int h = hb + 2*q + e;
                    const float w0r = wx0s[h],        w1r = wx0s[G_ + h];
                    const float w0z = wx0s[H_ + h],   w1z = wx0s[G_ + H_ + h];
                    const float w0n = wx0s[2*H_ + h], w1n = wx0s[G_ + 2*H_ + h];
                    const float bxr = bx0s[h], bxz = bx0s[H_ + h], bxn = bx0s[2*H_ + h];
                    const float bhr = bh0s[h], bhz = bh0s[H_ + h], bhn = bh0s[2*H_ + h];
                    float* hp = &h0s[h * COLS + cc];
                    float4 hold = *reinterpret_cast<float4*>(hp);
                    float holdv[4] = {hold.x, hold.y, hold.z, hold.w};
                    float hnew[4];
                    #pragma unroll
                    for (int col = 0; col < 4; ++col) {
                        const float grc = e ? gr[col].y : gr[col].x;
                        const float gzc = e ? gz[col].y : gz[col].x;
                        const float gnc = e ? gn[col].y : gn[col].x;
                        float ir = fmaf(xbv[col], w1r, fmaf(xav[col], w0r, bxr));
                        float iz = fmaf(xbv[col], w1z, fmaf(xav[col], w0z, bxz));
                        float in = fmaf(xbv[col], w1n, fmaf(xav[col], w0n, bxn));
                        float rr = sigm(ir + grc + bhr);
                        float zz = sigm(iz + gzc + bhz);
                        float nv = tanh_(fmaf(rr, gnc + bhn, in));
                        hnew[col] = fmaf(zz, holdv[col] - nv, nv);
                    }
                    *reinterpret_cast<float4*>(hp) =
                        make_float4(hnew[0], hnew[1], hnew[2], hnew[3]);
                }
            }
        }
        // h0s writes ordered before next accum by tile_iter's pre-accum sync.

        // ===== layer 1: gi1 = Wx1^T h0new (r,z,n) =====
        #pragma unroll
        for (int i = 0; i < 16; ++i) { aR[i] = 0ull; aZ[i] = 0ull; aN[i] = 0ull; }
        #pragma unroll 1
        for (int kt = 0; kt < 4; ++kt)
            tile_iter(h0s + kt * TROWS * COLS, aR, aZ, aN);

        // ===== layer 1: gh1 = Wh1^T h1 (r,z fused into aR/aZ; n into aN2) =====
        #pragma unroll
        for (int i = 0; i < 16; ++i) aN2[i] = 0ull;
        #pragma unroll 1
        for (int kt = 0; kt < 4; ++kt)
            tile_iter(h1s + kt * TROWS * COLS, aR, aZ, aN2);

        // ---- epilogue layer 1 ----
        #pragma unroll
        for (int q = 0; q < 4; ++q) {
            float2 gr[4], gz[4], gn[4], gm[4];
            #pragma unroll
            for (int col = 0; col < 4; ++col) {
                gr[col] = unpk(aR[col*4+q]);
                gz[col] = unpk(aZ[col*4+q]);
                gn[col] = unpk(aN[col*4+q]);
                gm[col] = unpk(aN2[col*4+q]);
            }
            #pragma unroll
            for (int e = 0; e < 2; ++e) {
                const int h = hb + 2*q + e;
                const float br  = bx1s[h] + bh1s[h];
                const float bz  = bx1s[H_ + h] + bh1s[H_ + h];
                const float bxn = bx1s[2*H_ + h], bhn = bh1s[2*H_ + h];
                float* hp = &h1s[h * COLS + cc];
                float4 hold = *reinterpret_cast<float4*>(hp);
                float holdv[4] = {hold.x, hold.y, hold.z, hold.w};
                float hnew[4];
                #pragma unroll
                for (int col = 0; col < 4; ++col) {
                    const float grc = e ? gr[col].y : gr[col].x;
                    const float gzc = e ? gz[col].y : gz[col].x;
                    const float gnc = e ? gn[col].y : gn[col].x;
                    const float gmc = e ? gm[col].y : gm[col].x;
                    float rr = sigm(grc + br);
                    float zz = sigm(gzc + bz);
                    float nv = tanh_(fmaf(rr, gmc + bhn, gnc + bxn));
                    hnew[col] = fmaf(zz, holdv[col] - nv, nv);
                }
                *reinterpret_cast<float4*>(hp) =
                    make_float4(hnew[0], hnew[1], hnew[2], hnew[3]);
            }
        }
    }

    asm volatile("cp.async.wait_group 0;" ::: "memory");
    __syncthreads();
    // output [2, B, H, N]
    const long ob = (long)bb * H_ * N_ + (col0 % N_);
    for (int i = tid; i < H_ * COLS; i += THREADS) {
        int h = i / COLS, c = i - (i / COLS) * COLS;
        out[ob + (long)h * N_ + c] = h0s[i];
        out[(long)B_ * H_ * N_ + ob + (long)h * N_ + c] = h1s[i];
    }
}

extern "C" void kernel_launch(void* const* d_in, const int* in_sizes, int n_in,
                              void* d_out, int out_size)
{
    (void)in_sizes; (void)n_in; (void)out_size;
    const float* x   = (const float*)d_in[0];
    const float* Wx0 = (const float*)d_in[1];
    const float* Wh0 = (const float*)d_in[2];
    const float* bx0 = (const float*)d_in[3];
    const float* bh0 = (const float*)d_in[4];
    const float* Wx1 = (const float*)d_in[5];
    const float* Wh1 = (const float*)d_in[6];
    const float* bx1 = (const float*)d_in[7];
    const float* bh1 = (const float*)d_in[8];
    float* out = (float*)d_out;

    const int smem_bytes = (2 * TILE_FLOATS + 2 * H_ * COLS + D_ * G_ + 4 * G_) * 4; // 173056
    cudaFuncSetAttribute(gru_stack_kernel,
                         cudaFuncAttributeMaxDynamicSharedMemorySize, smem_bytes);
    gru_stack_kernel<<<CTAS, THREADS, smem_bytes>>>(
        x, Wx0, Wh0, bx0, bh0, Wx1, Wh1, bx1, bh1, out);
}